// round 8
// baseline (speedup 1.0000x reference)
#include <cuda_runtime.h>
#include <cstdint>

#define N_NODES 50000
#define N_EDGES 800000
#define N_GRAPHS 128
#define IN_CH 31
#define C_PAD 32
#define HID 64
#define EPS_IN 1e-5f

#define SCAN_B 1024
#define SCAN_NB ((N_NODES + SCAN_B - 1) / SCAN_B)  // 49

typedef unsigned long long u64;

// ---------------- scratch (static device globals; no allocation) ----------------
__device__ float g_xpad[N_NODES * C_PAD];
__device__ float g_bufA[N_NODES * HID];
__device__ float g_bufB[N_NODES * HID];
__device__ float g_aggr[N_NODES * HID];
__device__ int g_deg[N_NODES];
__device__ int g_rowptr[N_NODES + 1];
__device__ int g_fill[N_NODES];
__device__ int g_csr[N_EDGES];
__device__ int g_part[SCAN_NB];
__device__ unsigned g_hbits[N_GRAPHS * 3 * HID];
__device__ float g_Wl1T[(3 * HID) * (2 * HID)];
__device__ float g_Wl2T[(2 * HID) * (HID / 2)];

// ---------------- f32x2 packed helpers ----------------
__device__ __forceinline__ u64 ffma2(u64 a, u64 b, u64 c) {
    u64 d;
    asm("fma.rn.f32x2 %0, %1, %2, %3;" : "=l"(d) : "l"(a), "l"(b), "l"(c));
    return d;
}
__device__ __forceinline__ float2 up2(u64 v) {
    float2 f;
    asm("mov.b64 {%0, %1}, %2;" : "=f"(f.x), "=f"(f.y) : "l"(v));
    return f;
}

// ---------------- prep: zero deg/hbits, transpose head weights, pad x ----------------
__global__ void k_prep(const float* __restrict__ x,
                       const float* __restrict__ Wl1,
                       const float* __restrict__ Wl2) {
    int i = blockIdx.x * 256 + threadIdx.x;
    if (i < N_NODES * C_PAD) {
        int n = i >> 5, c = i & 31;
        g_xpad[i] = (c < IN_CH) ? x[n * IN_CH + c] : 0.f;
    }
    if (i < N_NODES) g_deg[i] = 0;
    if (i < N_GRAPHS * 3 * HID) g_hbits[i] = 0u;
    if (i < 128 * 192) {
        int o = i / 192, c = i % 192;
        g_Wl1T[c * 128 + o] = Wl1[i];
    }
    if (i < 32 * 128) {
        int o = i / 128, c = i % 128;
        g_Wl2T[c * 32 + o] = Wl2[i];
    }
}

// ---------------- CSR build ----------------
__global__ void k_hist(const int* __restrict__ dst) {
    int e4 = blockIdx.x * 256 + threadIdx.x;
    if (e4 < N_EDGES / 4) {
        int4 d = __ldg((const int4*)dst + e4);
        atomicAdd(&g_deg[d.x], 1);
        atomicAdd(&g_deg[d.y], 1);
        atomicAdd(&g_deg[d.z], 1);
        atomicAdd(&g_deg[d.w], 1);
    }
}

__global__ void k_scanA() {
    __shared__ int s[SCAN_B];
    int i = blockIdx.x * SCAN_B + threadIdx.x;
    s[threadIdx.x] = (i < N_NODES) ? g_deg[i] : 0;
    __syncthreads();
    for (int off = SCAN_B / 2; off; off >>= 1) {
        if (threadIdx.x < off) s[threadIdx.x] += s[threadIdx.x + off];
        __syncthreads();
    }
    if (threadIdx.x == 0) g_part[blockIdx.x] = s[0];
}

// scanC with fused per-block offset computation (replaces old scanB)
__global__ void k_scanC() {
    __shared__ int s[SCAN_B];
    __shared__ int soff_sh;
    int tid = threadIdx.x;
    int b = blockIdx.x;
    if (tid == 0) soff_sh = 0;
    __syncthreads();
    if (tid < 64) {
        int pv = (tid < b && tid < SCAN_NB) ? g_part[tid] : 0;
#pragma unroll
        for (int off = 16; off; off >>= 1) pv += __shfl_xor_sync(0xFFFFFFFFu, pv, off);
        if ((tid & 31) == 0) atomicAdd(&soff_sh, pv);
    }
    int i = b * SCAN_B + tid;
    int v = (i < N_NODES) ? g_deg[i] : 0;
    s[tid] = v;
    __syncthreads();
    for (int off = 1; off < SCAN_B; off <<= 1) {
        int a = (tid >= off) ? s[tid - off] : 0;
        __syncthreads();
        s[tid] += a;
        __syncthreads();
    }
    if (i < N_NODES) {
        int incl = s[tid] + soff_sh;
        g_rowptr[i + 1] = incl;
        g_fill[i] = incl - v;
    }
    if (b == 0 && tid == 0) g_rowptr[0] = 0;
}

__global__ void k_scatter(const int* __restrict__ src, const int* __restrict__ dst) {
    int e4 = blockIdx.x * 256 + threadIdx.x;
    if (e4 < N_EDGES / 4) {
        int4 d = __ldg((const int4*)dst + e4);
        int4 sv = __ldg((const int4*)src + e4);
        int p0 = atomicAdd(&g_fill[d.x], 1);
        int p1 = atomicAdd(&g_fill[d.y], 1);
        int p2 = atomicAdd(&g_fill[d.z], 1);
        int p3 = atomicAdd(&g_fill[d.w], 1);
        g_csr[p0] = sv.x;
        g_csr[p1] = sv.y;
        g_csr[p2] = sv.z;
        g_csr[p3] = sv.w;
    }
}

// ---------------- one-pass segment softmax aggregation ----------------
// aggr[n,c] = sum_e v*exp(t*v) / sum_e exp(t*v)  (shift-invariant; logits bounded)
// Software-pipelined csr prefetch; masked chunk tail (no cleanup loop).
__global__ __launch_bounds__(256) void k_aggr32(const float* __restrict__ xin,
                                                const float* __restrict__ tptr,
                                                float* __restrict__ aggr) {
    int node = (blockIdx.x * 256 + threadIdx.x) >> 5;
    int lane = threadIdx.x & 31;
    if (node >= N_NODES) return;
    float t = __ldg(tptr);
    int beg = __ldg(&g_rowptr[node]);
    int end = __ldg(&g_rowptr[node + 1]);
    float num = 0.f, den = 0.f;
    if (beg < end) {
        int e1 = end - 1;
        int k = beg;
        int i0 = __ldg(&g_csr[k]);
        int i1 = __ldg(&g_csr[min(k + 1, e1)]);
        int i2 = __ldg(&g_csr[min(k + 2, e1)]);
        int i3 = __ldg(&g_csr[min(k + 3, e1)]);
        while (k < end) {
            int j0 = i0, j1 = i1, j2 = i2, j3 = i3;
            int kc = k;
            k += 4;
            if (k < end) {
                i0 = __ldg(&g_csr[k]);
                i1 = __ldg(&g_csr[min(k + 1, e1)]);
                i2 = __ldg(&g_csr[min(k + 2, e1)]);
                i3 = __ldg(&g_csr[min(k + 3, e1)]);
            }
            float v0 = __ldg(xin + j0 * C_PAD + lane);
            float v1 = __ldg(xin + j1 * C_PAD + lane);
            float v2 = __ldg(xin + j2 * C_PAD + lane);
            float v3 = __ldg(xin + j3 * C_PAD + lane);
            float m1 = (kc + 1 < end) ? 1.f : 0.f;
            float m2 = (kc + 2 < end) ? 1.f : 0.f;
            float m3 = (kc + 3 < end) ? 1.f : 0.f;
            float e;
            e = __expf(v0 * t);      den += e; num += v0 * e;
            e = __expf(v1 * t) * m1; den += e; num += v1 * e;
            e = __expf(v2 * t) * m2; den += e; num += v2 * e;
            e = __expf(v3 * t) * m3; den += e; num += v3 * e;
        }
    }
    aggr[node * C_PAD + lane] = (den > 0.f) ? num / den : 0.f;
}

__global__ __launch_bounds__(256) void k_aggr64(const float* __restrict__ xin,
                                                const float* __restrict__ tptr,
                                                float* __restrict__ aggr) {
    int node = (blockIdx.x * 256 + threadIdx.x) >> 5;
    int lane = threadIdx.x & 31;
    if (node >= N_NODES) return;
    float t = __ldg(tptr);
    int beg = __ldg(&g_rowptr[node]);
    int end = __ldg(&g_rowptr[node + 1]);
    int co = 2 * lane;
    float nx = 0.f, ny = 0.f, dx = 0.f, dy = 0.f;
    if (beg < end) {
        int e1 = end - 1;
        int k = beg;
        int i0 = __ldg(&g_csr[k]);
        int i1 = __ldg(&g_csr[min(k + 1, e1)]);
        int i2 = __ldg(&g_csr[min(k + 2, e1)]);
        int i3 = __ldg(&g_csr[min(k + 3, e1)]);
        while (k < end) {
            int j0 = i0, j1 = i1, j2 = i2, j3 = i3;
            int kc = k;
            k += 4;
            if (k < end) {
                i0 = __ldg(&g_csr[k]);
                i1 = __ldg(&g_csr[min(k + 1, e1)]);
                i2 = __ldg(&g_csr[min(k + 2, e1)]);
                i3 = __ldg(&g_csr[min(k + 3, e1)]);
            }
            float2 v0 = *(const float2*)(xin + j0 * HID + co);
            float2 v1 = *(const float2*)(xin + j1 * HID + co);
            float2 v2 = *(const float2*)(xin + j2 * HID + co);
            float2 v3 = *(const float2*)(xin + j3 * HID + co);
            float m1 = (kc + 1 < end) ? 1.f : 0.f;
            float m2 = (kc + 2 < end) ? 1.f : 0.f;
            float m3 = (kc + 3 < end) ? 1.f : 0.f;
            float e;
            e = __expf(v0.x * t);      dx += e; nx += v0.x * e;
            e = __expf(v0.y * t);      dy += e; ny += v0.y * e;
            e = __expf(v1.x * t) * m1; dx += e; nx += v1.x * e;
            e = __expf(v1.y * t) * m1; dy += e; ny += v1.y * e;
            e = __expf(v2.x * t) * m2; dx += e; nx += v2.x * e;
            e = __expf(v2.y * t) * m2; dy += e; ny += v2.y * e;
            e = __expf(v3.x * t) * m3; dx += e; nx += v3.x * e;
            e = __expf(v3.y * t) * m3; dy += e; ny += v3.y * e;
        }
    }
    float2 o;
    o.x = (dx > 0.f) ? nx / dx : 0.f;
    o.y = (dy > 0.f) ? ny / dy : 0.f;
    *(float2*)(aggr + node * HID + co) = o;
}

// ---------------- fused dual-GEMM + instance-norm + relu + per-graph segmax -----------
// Channel-pair f32x2 packing: input float2s ARE the packed operand (no pk movs).
// 256 threads = 8 warps; warp owns 8 nodes; lane owns outputs (2*lane, 2*lane+1).
// Warp-local running segmax (batch sorted) -> ~7x fewer global atomics.
template <int C, int CREAL>
__global__ __launch_bounds__(256) void k_lin(const float* __restrict__ xin,
                                             const float* __restrict__ aggr,
                                             const float* __restrict__ Wr,
                                             const float* __restrict__ br,
                                             const float* __restrict__ Ws,
                                             const int* __restrict__ batch,
                                             int loff,
                                             float* __restrict__ y) {
    constexpr int CP = C / 2;
    __shared__ __align__(16) float2 sWr2[CP * HID];  // [cp][o] = (W[2cp][o], W[2cp+1][o])
    __shared__ __align__(16) float2 sWs2[CP * HID];
    __shared__ float sb[HID];
    int tid = threadIdx.x;
    for (int i = tid; i < CP * HID; i += 256) {
        int cp = i / HID, o = i - cp * HID;
        int c0 = 2 * cp, c1 = c0 + 1;
        float2 wr, ws;
        wr.x = (c0 < CREAL) ? Wr[o * CREAL + c0] : 0.f;
        wr.y = (c1 < CREAL) ? Wr[o * CREAL + c1] : 0.f;
        ws.x = (c0 < CREAL) ? Ws[o * CREAL + c0] : 0.f;
        ws.y = (c1 < CREAL) ? Ws[o * CREAL + c1] : 0.f;
        sWr2[i] = wr;
        sWs2[i] = ws;
    }
    if (tid < HID) sb[tid] = br[tid];
    __syncthreads();

    int lane = tid & 31;
    int wrp = tid >> 5;
    int o0 = 2 * lane;
    int n0 = blockIdx.x * 64 + wrp * 8;

    int row[8];
#pragma unroll
    for (int n = 0; n < 8; n++) {
        int node = n0 + n;
        if (node > N_NODES - 1) node = N_NODES - 1;
        row[n] = node * C;
    }
    u64 a0[8], a1[8];
#pragma unroll
    for (int n = 0; n < 8; n++) { a0[n] = 0ull; a1[n] = 0ull; }

#pragma unroll 4
    for (int cs = 0; cs < C; cs += 4) {
        int cp = cs >> 1;
        ulonglong2 wrA = *(const ulonglong2*)&sWr2[cp * HID + o0];
        ulonglong2 wrB = *(const ulonglong2*)&sWr2[(cp + 1) * HID + o0];
        ulonglong2 wsA = *(const ulonglong2*)&sWs2[cp * HID + o0];
        ulonglong2 wsB = *(const ulonglong2*)&sWs2[(cp + 1) * HID + o0];
#pragma unroll
        for (int n = 0; n < 8; n++) {
            ulonglong2 av = *(const ulonglong2*)(aggr + row[n] + cs);
            ulonglong2 xv = *(const ulonglong2*)(xin + row[n] + cs);
            a0[n] = ffma2(av.x, wrA.x, a0[n]);
            a0[n] = ffma2(av.y, wrB.x, a0[n]);
            a0[n] = ffma2(xv.x, wsA.x, a0[n]);
            a0[n] = ffma2(xv.y, wsB.x, a0[n]);
            a1[n] = ffma2(av.x, wrA.y, a1[n]);
            a1[n] = ffma2(av.y, wrB.y, a1[n]);
            a1[n] = ffma2(xv.x, wsA.y, a1[n]);
            a1[n] = ffma2(xv.y, wsB.y, a1[n]);
        }
    }

    float b0 = sb[o0], b1 = sb[o0 + 1];
    float gm0 = 0.f, gm1 = 0.f;
    int curg = -1;
#pragma unroll
    for (int n = 0; n < 8; n++) {
        int node = n0 + n;
        if (node >= N_NODES) break;  // node uniform across warp
        float2 p0 = up2(a0[n]);
        float2 p1 = up2(a1[n]);
        float f0 = p0.x + p0.y + b0;
        float f1 = p1.x + p1.y + b1;
        float sum = f0 + f1;
#pragma unroll
        for (int off = 16; off; off >>= 1) sum += __shfl_xor_sync(0xFFFFFFFFu, sum, off);
        float mu = sum * (1.0f / HID);
        float d0 = f0 - mu, d1 = f1 - mu;
        float q = d0 * d0 + d1 * d1;
#pragma unroll
        for (int off = 16; off; off >>= 1) q += __shfl_xor_sync(0xFFFFFFFFu, q, off);
        float r = rsqrtf(q * (1.0f / HID) + EPS_IN);
        float2 o;
        o.x = fmaxf(d0 * r, 0.f);
        o.y = fmaxf(d1 * r, 0.f);
        *(float2*)&y[(size_t)node * HID + o0] = o;
        int g = __ldg(&batch[node]);
        if (g != curg) {
            if (curg >= 0) {
                unsigned* hrow = g_hbits + curg * (3 * HID) + loff + o0;
                atomicMax(&hrow[0], __float_as_uint(gm0));
                atomicMax(&hrow[1], __float_as_uint(gm1));
            }
            curg = g;
            gm0 = o.x;
            gm1 = o.y;
        } else {
            gm0 = fmaxf(gm0, o.x);
            gm1 = fmaxf(gm1, o.y);
        }
    }
    if (curg >= 0) {
        unsigned* hrow = g_hbits + curg * (3 * HID) + loff + o0;
        atomicMax(&hrow[0], __float_as_uint(gm0));
        atomicMax(&hrow[1], __float_as_uint(gm1));
    }
}

// ---------------- head MLP: one block per graph ----------------
__global__ __launch_bounds__(192) void k_final(const float* __restrict__ bl1,
                                               const float* __restrict__ bl2,
                                               float* __restrict__ out) {
    __shared__ float sh[3 * HID];
    __shared__ float sz1[2 * HID];
    __shared__ float sz2[HID / 2];
    int g = blockIdx.x;
    int tid = threadIdx.x;
    sh[tid] = __uint_as_float(g_hbits[g * (3 * HID) + tid]);
    __syncthreads();
    if (tid < 2 * HID) {
        float acc = bl1[tid];
#pragma unroll 4
        for (int c = 0; c < 3 * HID; c++) acc += sh[c] * g_Wl1T[c * (2 * HID) + tid];
        sz1[tid] = fmaxf(acc, 0.f);
    }
    __syncthreads();
    if (tid < HID / 2) {
        float acc = bl2[tid];
#pragma unroll 4
        for (int c = 0; c < 2 * HID; c++) acc += sz1[c] * g_Wl2T[c * (HID / 2) + tid];
        sz2[tid] = acc;
    }
    __syncthreads();
    if (tid < 32) {
        float v = sz2[tid];
        float q = v * v;
#pragma unroll
        for (int o = 16; o; o >>= 1) q += __shfl_xor_sync(0xFFFFFFFFu, q, o);
        float nrm = fmaxf(sqrtf(q), 1e-12f);
        out[g * 32 + tid] = v / nrm;
    }
}

// ---------------- launch ----------------
extern "C" void kernel_launch(void* const* d_in, const int* in_sizes, int n_in,
                              void* d_out, int out_size) {
    const float* x = (const float*)d_in[0];
    const int* ei = (const int*)d_in[1];
    const int* src = ei;
    const int* dst = ei + N_EDGES;
    const int* batch = (const int*)d_in[2];
    const float* t = (const float*)d_in[3];
    const float* W1r = (const float*)d_in[4];
    const float* b1 = (const float*)d_in[5];
    const float* W1s = (const float*)d_in[6];
    const float* W2r = (const float*)d_in[7];
    const float* b2 = (const float*)d_in[8];
    const float* W2s = (const float*)d_in[9];
    const float* W3r = (const float*)d_in[10];
    const float* b3 = (const float*)d_in[11];
    const float* W3s = (const float*)d_in[12];
    const float* Wl1 = (const float*)d_in[13];
    const float* bl1 = (const float*)d_in[14];
    const float* Wl2 = (const float*)d_in[15];
    const float* bl2 = (const float*)d_in[16];
    float* out = (float*)d_out;

    float *xpad, *bufA, *bufB, *aggr;
    cudaGetSymbolAddress((void**)&xpad, g_xpad);
    cudaGetSymbolAddress((void**)&bufA, g_bufA);
    cudaGetSymbolAddress((void**)&bufB, g_bufB);
    cudaGetSymbolAddress((void**)&aggr, g_aggr);

    const int PB = (N_NODES * C_PAD + 255) / 256;   // 6250
    const int E4B = (N_EDGES / 4 + 255) / 256;      // 782
    const int WB = (N_NODES * 32 + 255) / 256;      // warp-per-node: 6250
    const int LB = (N_NODES + 63) / 64;             // 782

    k_prep<<<PB, 256>>>(x, Wl1, Wl2);
    k_hist<<<E4B, 256>>>(dst);
    k_scanA<<<SCAN_NB, SCAN_B>>>();
    k_scanC<<<SCAN_NB, SCAN_B>>>();
    k_scatter<<<E4B, 256>>>(src, dst);

    // layer 1 (padded to 32 ch; channel 31 is exactly zero everywhere)
    k_aggr32<<<WB, 256>>>(xpad, t, aggr);
    k_lin<C_PAD, IN_CH><<<LB, 256>>>(xpad, aggr, W1r, b1, W1s, batch, 0, bufA);

    // layer 2
    k_aggr64<<<WB, 256>>>(bufA, t, aggr);
    k_lin<HID, HID><<<LB, 256>>>(bufA, aggr, W2r, b2, W2s, batch, HID, bufB);

    // layer 3
    k_aggr64<<<WB, 256>>>(bufB, t, aggr);
    k_lin<HID, HID><<<LB, 256>>>(bufB, aggr, W3r, b3, W3s, batch, 2 * HID, bufA);

    k_final<<<N_GRAPHS, 192>>>(bl1, bl2, out);
    (void)in_sizes; (void)n_in; (void)out_size;
}

// round 9
// speedup vs baseline: 1.3415x; 1.3415x over previous
#include <cuda_runtime.h>
#include <cstdint>

#define N_NODES 50000
#define N_EDGES 800000
#define N_GRAPHS 128
#define IN_CH 31
#define C_PAD 32
#define HID 64
#define EPS_IN 1e-5f

#define SCAN_B 1024
#define SCAN_NB ((N_NODES + SCAN_B - 1) / SCAN_B)  // 49

typedef unsigned long long u64;

// ---------------- scratch (static device globals; no allocation) ----------------
__device__ float g_xpad[N_NODES * C_PAD];
__device__ float g_bufA[N_NODES * HID];
__device__ float g_bufB[N_NODES * HID];
__device__ float g_aggr[N_NODES * HID];
__device__ int g_deg[N_NODES];
__device__ int g_rowptr[N_NODES + 1];
__device__ int g_fill[N_NODES];
__device__ int g_csr[N_EDGES];
__device__ int g_part[SCAN_NB];
__device__ unsigned g_hbits[N_GRAPHS * 3 * HID];
__device__ float g_Wl1T[(3 * HID) * (2 * HID)];
__device__ float g_Wl2T[(2 * HID) * (HID / 2)];

// ---------------- f32x2 packed helpers ----------------
__device__ __forceinline__ u64 pk2(float v) {
    u64 r;
    asm("mov.b64 %0, {%1, %1};" : "=l"(r) : "f"(v));
    return r;
}
__device__ __forceinline__ u64 ffma2(u64 a, u64 b, u64 c) {
    u64 d;
    asm("fma.rn.f32x2 %0, %1, %2, %3;" : "=l"(d) : "l"(a), "l"(b), "l"(c));
    return d;
}
__device__ __forceinline__ float2 up2(u64 v) {
    float2 f;
    asm("mov.b64 {%0, %1}, %2;" : "=f"(f.x), "=f"(f.y) : "l"(v));
    return f;
}

// ---------------- prep: zero deg/hbits, transpose head weights, pad x ----------------
__global__ void k_prep(const float* __restrict__ x,
                       const float* __restrict__ Wl1,
                       const float* __restrict__ Wl2) {
    int i = blockIdx.x * 256 + threadIdx.x;
    if (i < N_NODES * C_PAD) {
        int n = i >> 5, c = i & 31;
        g_xpad[i] = (c < IN_CH) ? x[n * IN_CH + c] : 0.f;
    }
    if (i < N_NODES) g_deg[i] = 0;
    if (i < N_GRAPHS * 3 * HID) g_hbits[i] = 0u;
    if (i < 128 * 192) {
        int o = i / 192, c = i % 192;
        g_Wl1T[c * 128 + o] = Wl1[i];
    }
    if (i < 32 * 128) {
        int o = i / 128, c = i % 128;
        g_Wl2T[c * 32 + o] = Wl2[i];
    }
}

// ---------------- CSR build ----------------
__global__ void k_hist(const int* __restrict__ dst) {
    int e4 = blockIdx.x * 256 + threadIdx.x;
    if (e4 < N_EDGES / 4) {
        int4 d = __ldg((const int4*)dst + e4);
        atomicAdd(&g_deg[d.x], 1);
        atomicAdd(&g_deg[d.y], 1);
        atomicAdd(&g_deg[d.z], 1);
        atomicAdd(&g_deg[d.w], 1);
    }
}

__global__ void k_scanA() {
    __shared__ int s[SCAN_B];
    int i = blockIdx.x * SCAN_B + threadIdx.x;
    s[threadIdx.x] = (i < N_NODES) ? g_deg[i] : 0;
    __syncthreads();
    for (int off = SCAN_B / 2; off; off >>= 1) {
        if (threadIdx.x < off) s[threadIdx.x] += s[threadIdx.x + off];
        __syncthreads();
    }
    if (threadIdx.x == 0) g_part[blockIdx.x] = s[0];
}

// block scan with fused per-block offset (sums g_part[0..b-1] in-kernel)
__global__ void k_scanC() {
    __shared__ int s[SCAN_B];
    __shared__ int soff_sh;
    int tid = threadIdx.x;
    int b = blockIdx.x;
    if (tid == 0) soff_sh = 0;
    __syncthreads();
    if (tid < 64) {
        int pv = (tid < b && tid < SCAN_NB) ? g_part[tid] : 0;
#pragma unroll
        for (int off = 16; off; off >>= 1) pv += __shfl_xor_sync(0xFFFFFFFFu, pv, off);
        if ((tid & 31) == 0) atomicAdd(&soff_sh, pv);
    }
    int i = b * SCAN_B + tid;
    int v = (i < N_NODES) ? g_deg[i] : 0;
    s[tid] = v;
    __syncthreads();
    for (int off = 1; off < SCAN_B; off <<= 1) {
        int a = (tid >= off) ? s[tid - off] : 0;
        __syncthreads();
        s[tid] += a;
        __syncthreads();
    }
    if (i < N_NODES) {
        int incl = s[tid] + soff_sh;
        g_rowptr[i + 1] = incl;
        g_fill[i] = incl - v;
    }
    if (b == 0 && tid == 0) g_rowptr[0] = 0;
}

__global__ void k_scatter(const int* __restrict__ src, const int* __restrict__ dst) {
    int e4 = blockIdx.x * 256 + threadIdx.x;
    if (e4 < N_EDGES / 4) {
        int4 d = __ldg((const int4*)dst + e4);
        int4 sv = __ldg((const int4*)src + e4);
        int p0 = atomicAdd(&g_fill[d.x], 1);
        int p1 = atomicAdd(&g_fill[d.y], 1);
        int p2 = atomicAdd(&g_fill[d.z], 1);
        int p3 = atomicAdd(&g_fill[d.w], 1);
        g_csr[p0] = sv.x;
        g_csr[p1] = sv.y;
        g_csr[p2] = sv.z;
        g_csr[p3] = sv.w;
    }
}

// ---------------- one-pass segment softmax aggregation (proven round-5 form) --------
// aggr[n,c] = sum_e v*exp(t*v) / sum_e exp(t*v)  (shift-invariant; logits bounded)
__global__ __launch_bounds__(256) void k_aggr32(const float* __restrict__ xin,
                                                const float* __restrict__ tptr,
                                                float* __restrict__ aggr) {
    int node = (blockIdx.x * 256 + threadIdx.x) >> 5;
    int lane = threadIdx.x & 31;
    if (node >= N_NODES) return;
    float t = __ldg(tptr);
    int beg = g_rowptr[node];
    int end = g_rowptr[node + 1];
    float num = 0.f, den = 0.f;
    int k = beg;
#define ACC1(v)                    \
    {                              \
        float e = __expf((v) * t); \
        den += e;                  \
        num += (v) * e;            \
    }
    for (; k + 4 <= end; k += 4) {
        int s0 = g_csr[k], s1 = g_csr[k + 1], s2 = g_csr[k + 2], s3 = g_csr[k + 3];
        float v0 = xin[(size_t)s0 * C_PAD + lane];
        float v1 = xin[(size_t)s1 * C_PAD + lane];
        float v2 = xin[(size_t)s2 * C_PAD + lane];
        float v3 = xin[(size_t)s3 * C_PAD + lane];
        ACC1(v0) ACC1(v1) ACC1(v2) ACC1(v3)
    }
    for (; k < end; k++) {
        float v = xin[(size_t)g_csr[k] * C_PAD + lane];
        ACC1(v)
    }
#undef ACC1
    aggr[(size_t)node * C_PAD + lane] = (den > 0.f) ? num / den : 0.f;
}

__global__ __launch_bounds__(256) void k_aggr64(const float* __restrict__ xin,
                                                const float* __restrict__ tptr,
                                                float* __restrict__ aggr) {
    int node = (blockIdx.x * 256 + threadIdx.x) >> 5;
    int lane = threadIdx.x & 31;
    if (node >= N_NODES) return;
    float t = __ldg(tptr);
    int beg = g_rowptr[node];
    int end = g_rowptr[node + 1];
    float nx = 0.f, ny = 0.f, dx = 0.f, dy = 0.f;
    int co = 2 * lane;
    int k = beg;
#define ACC2(v)                       \
    {                                 \
        float e0 = __expf((v).x * t); \
        float e1 = __expf((v).y * t); \
        dx += e0;                     \
        nx += (v).x * e0;             \
        dy += e1;                     \
        ny += (v).y * e1;             \
    }
    for (; k + 4 <= end; k += 4) {
        int s0 = g_csr[k], s1 = g_csr[k + 1], s2 = g_csr[k + 2], s3 = g_csr[k + 3];
        float2 v0 = *(const float2*)(xin + (size_t)s0 * HID + co);
        float2 v1 = *(const float2*)(xin + (size_t)s1 * HID + co);
        float2 v2 = *(const float2*)(xin + (size_t)s2 * HID + co);
        float2 v3 = *(const float2*)(xin + (size_t)s3 * HID + co);
        ACC2(v0) ACC2(v1) ACC2(v2) ACC2(v3)
    }
    for (; k < end; k++) {
        int s = g_csr[k];
        float2 v = *(const float2*)(xin + (size_t)s * HID + co);
        ACC2(v)
    }
#undef ACC2
    float2 o;
    o.x = (dx > 0.f) ? nx / dx : 0.f;
    o.y = (dy > 0.f) ? ny / dy : 0.f;
    *(float2*)(aggr + (size_t)node * HID + co) = o;
}

// ---------------- fused dual-GEMM + instance-norm + relu + per-graph segmax -----------
// PROVEN mainloop (round-5): 16 o-quads x 16 node-groups of 8 nodes, pk2+ffma2.
// NEW epilogue: running per-group segmax across the 8 consecutive nodes (batch
// sorted), flush atomics only on graph change -> ~7x fewer global atomics.
template <int C, int CREAL>
__global__ __launch_bounds__(256) void k_lin(const float* __restrict__ xin,
                                             const float* __restrict__ aggr,
                                             const float* __restrict__ Wr,
                                             const float* __restrict__ br,
                                             const float* __restrict__ Ws,
                                             const int* __restrict__ batch,
                                             int loff,
                                             float* __restrict__ y) {
    __shared__ __align__(16) float sWr[C * HID];  // [c][o]
    __shared__ __align__(16) float sWs[C * HID];  // [c][o]
    __shared__ __align__(16) float sb[HID];
    int tid = threadIdx.x;
    for (int i = tid; i < C * HID; i += 256) {
        int o = i / C, c = i % C;
        float wr = (c < CREAL) ? Wr[o * CREAL + c] : 0.f;
        float ws = (c < CREAL) ? Ws[o * CREAL + c] : 0.f;
        sWr[c * HID + o] = wr;
        sWs[c * HID + o] = ws;
    }
    if (tid < HID) sb[tid] = br[tid];
    __syncthreads();

    int oq = tid & 15;
    int ng = tid >> 4;
    int o0 = oq * 4;
    int n0 = blockIdx.x * 128 + ng * 8;

    size_t rowoff[8];
#pragma unroll
    for (int n = 0; n < 8; n++) {
        int node = n0 + n;
        if (node >= N_NODES) node = N_NODES - 1;
        rowoff[n] = (size_t)node * C;
    }

    ulonglong2 b2 = *(const ulonglong2*)&sb[o0];
    u64 accA[8], accB[8];
#pragma unroll
    for (int n = 0; n < 8; n++) { accA[n] = b2.x; accB[n] = b2.y; }

    for (int c = 0; c < C; c += 4) {
        ulonglong2 wr0 = *(const ulonglong2*)&sWr[(c + 0) * HID + o0];
        ulonglong2 wr1 = *(const ulonglong2*)&sWr[(c + 1) * HID + o0];
        ulonglong2 wr2 = *(const ulonglong2*)&sWr[(c + 2) * HID + o0];
        ulonglong2 wr3 = *(const ulonglong2*)&sWr[(c + 3) * HID + o0];
        ulonglong2 ws0 = *(const ulonglong2*)&sWs[(c + 0) * HID + o0];
        ulonglong2 ws1 = *(const ulonglong2*)&sWs[(c + 1) * HID + o0];
        ulonglong2 ws2 = *(const ulonglong2*)&sWs[(c + 2) * HID + o0];
        ulonglong2 ws3 = *(const ulonglong2*)&sWs[(c + 3) * HID + o0];
#pragma unroll
        for (int n = 0; n < 8; n++) {
            float4 av = *(const float4*)(aggr + rowoff[n] + c);
            float4 xv = *(const float4*)(xin + rowoff[n] + c);
            u64 p;
            p = pk2(av.x); accA[n] = ffma2(p, wr0.x, accA[n]); accB[n] = ffma2(p, wr0.y, accB[n]);
            p = pk2(xv.x); accA[n] = ffma2(p, ws0.x, accA[n]); accB[n] = ffma2(p, ws0.y, accB[n]);
            p = pk2(av.y); accA[n] = ffma2(p, wr1.x, accA[n]); accB[n] = ffma2(p, wr1.y, accB[n]);
            p = pk2(xv.y); accA[n] = ffma2(p, ws1.x, accA[n]); accB[n] = ffma2(p, ws1.y, accB[n]);
            p = pk2(av.z); accA[n] = ffma2(p, wr2.x, accA[n]); accB[n] = ffma2(p, wr2.y, accB[n]);
            p = pk2(xv.z); accA[n] = ffma2(p, ws2.x, accA[n]); accB[n] = ffma2(p, ws2.y, accB[n]);
            p = pk2(av.w); accA[n] = ffma2(p, wr3.x, accA[n]); accB[n] = ffma2(p, wr3.y, accB[n]);
            p = pk2(xv.w); accA[n] = ffma2(p, ws3.x, accA[n]); accB[n] = ffma2(p, ws3.y, accB[n]);
        }
    }

    // epilogue: instance norm (16-lane group) + relu + store + batched segmax
    float4 gm = make_float4(0.f, 0.f, 0.f, 0.f);
    int curg = -1;
#pragma unroll
    for (int n = 0; n < 8; n++) {
        int node = n0 + n;
        if (node >= N_NODES) break;  // uniform across the 16-lane group
        float2 p0 = up2(accA[n]);
        float2 p1 = up2(accB[n]);
        float sum = p0.x + p0.y + p1.x + p1.y;
#pragma unroll
        for (int off = 8; off; off >>= 1) sum += __shfl_xor_sync(0xFFFFFFFFu, sum, off);
        float mu = sum * (1.0f / HID);
        float d0 = p0.x - mu, d1 = p0.y - mu, d2 = p1.x - mu, d3 = p1.y - mu;
        float q = d0 * d0 + d1 * d1 + d2 * d2 + d3 * d3;
#pragma unroll
        for (int off = 8; off; off >>= 1) q += __shfl_xor_sync(0xFFFFFFFFu, q, off);
        float r = rsqrtf(q * (1.0f / HID) + EPS_IN);
        float4 o;
        o.x = fmaxf(d0 * r, 0.f);
        o.y = fmaxf(d1 * r, 0.f);
        o.z = fmaxf(d2 * r, 0.f);
        o.w = fmaxf(d3 * r, 0.f);
        *(float4*)&y[(size_t)node * HID + o0] = o;
        int g = __ldg(&batch[node]);
        if (g != curg) {
            if (curg >= 0) {
                unsigned* hrow = g_hbits + curg * (3 * HID) + loff + o0;
                atomicMax(&hrow[0], __float_as_uint(gm.x));
                atomicMax(&hrow[1], __float_as_uint(gm.y));
                atomicMax(&hrow[2], __float_as_uint(gm.z));
                atomicMax(&hrow[3], __float_as_uint(gm.w));
            }
            curg = g;
            gm = o;
        } else {
            gm.x = fmaxf(gm.x, o.x);
            gm.y = fmaxf(gm.y, o.y);
            gm.z = fmaxf(gm.z, o.z);
            gm.w = fmaxf(gm.w, o.w);
        }
    }
    if (curg >= 0) {
        unsigned* hrow = g_hbits + curg * (3 * HID) + loff + o0;
        atomicMax(&hrow[0], __float_as_uint(gm.x));
        atomicMax(&hrow[1], __float_as_uint(gm.y));
        atomicMax(&hrow[2], __float_as_uint(gm.z));
        atomicMax(&hrow[3], __float_as_uint(gm.w));
    }
}

// ---------------- head MLP: one block per graph ----------------
__global__ __launch_bounds__(192) void k_final(const float* __restrict__ bl1,
                                               const float* __restrict__ bl2,
                                               float* __restrict__ out) {
    __shared__ float sh[3 * HID];
    __shared__ float sz1[2 * HID];
    __shared__ float sz2[HID / 2];
    int g = blockIdx.x;
    int tid = threadIdx.x;
    sh[tid] = __uint_as_float(g_hbits[g * (3 * HID) + tid]);
    __syncthreads();
    if (tid < 2 * HID) {
        float acc = bl1[tid];
#pragma unroll 4
        for (int c = 0; c < 3 * HID; c++) acc += sh[c] * g_Wl1T[c * (2 * HID) + tid];
        sz1[tid] = fmaxf(acc, 0.f);
    }
    __syncthreads();
    if (tid < HID / 2) {
        float acc = bl2[tid];
#pragma unroll 4
        for (int c = 0; c < 2 * HID; c++) acc += sz1[c] * g_Wl2T[c * (HID / 2) + tid];
        sz2[tid] = acc;
    }
    __syncthreads();
    if (tid < 32) {
        float v = sz2[tid];
        float q = v * v;
#pragma unroll
        for (int o = 16; o; o >>= 1) q += __shfl_xor_sync(0xFFFFFFFFu, q, o);
        float nrm = fmaxf(sqrtf(q), 1e-12f);
        out[g * 32 + tid] = v / nrm;
    }
}

// ---------------- launch ----------------
extern "C" void kernel_launch(void* const* d_in, const int* in_sizes, int n_in,
                              void* d_out, int out_size) {
    const float* x = (const float*)d_in[0];
    const int* ei = (const int*)d_in[1];
    const int* src = ei;
    const int* dst = ei + N_EDGES;
    const int* batch = (const int*)d_in[2];
    const float* t = (const float*)d_in[3];
    const float* W1r = (const float*)d_in[4];
    const float* b1 = (const float*)d_in[5];
    const float* W1s = (const float*)d_in[6];
    const float* W2r = (const float*)d_in[7];
    const float* b2 = (const float*)d_in[8];
    const float* W2s = (const float*)d_in[9];
    const float* W3r = (const float*)d_in[10];
    const float* b3 = (const float*)d_in[11];
    const float* W3s = (const float*)d_in[12];
    const float* Wl1 = (const float*)d_in[13];
    const float* bl1 = (const float*)d_in[14];
    const float* Wl2 = (const float*)d_in[15];
    const float* bl2 = (const float*)d_in[16];
    float* out = (float*)d_out;

    float *xpad, *bufA, *bufB, *aggr;
    cudaGetSymbolAddress((void**)&xpad, g_xpad);
    cudaGetSymbolAddress((void**)&bufA, g_bufA);
    cudaGetSymbolAddress((void**)&bufB, g_bufB);
    cudaGetSymbolAddress((void**)&aggr, g_aggr);

    const int PB = (N_NODES * C_PAD + 255) / 256;  // 6250
    const int E4B = (N_EDGES / 4 + 255) / 256;     // 782
    const int WB = (N_NODES * 32 + 255) / 256;     // warp-per-node: 6250
    const int LB = (N_NODES + 127) / 128;          // 391

    k_prep<<<PB, 256>>>(x, Wl1, Wl2);
    k_hist<<<E4B, 256>>>(dst);
    k_scanA<<<SCAN_NB, SCAN_B>>>();
    k_scanC<<<SCAN_NB, SCAN_B>>>();
    k_scatter<<<E4B, 256>>>(src, dst);

    // layer 1 (padded to 32 ch; channel 31 is exactly zero everywhere)
    k_aggr32<<<WB, 256>>>(xpad, t, aggr);
    k_lin<C_PAD, IN_CH><<<LB, 256>>>(xpad, aggr, W1r, b1, W1s, batch, 0, bufA);

    // layer 2
    k_aggr64<<<WB, 256>>>(bufA, t, aggr);
    k_lin<HID, HID><<<LB, 256>>>(bufA, aggr, W2r, b2, W2s, batch, HID, bufB);

    // layer 3
    k_aggr64<<<WB, 256>>>(bufB, t, aggr);
    k_lin<HID, HID><<<LB, 256>>>(bufB, aggr, W3r, b3, W3s, batch, 2 * HID, bufA);

    k_final<<<N_GRAPHS, 192>>>(bl1, bl2, out);
    (void)in_sizes; (void)n_in; (void)out_size;
}

// round 10
// speedup vs baseline: 1.4060x; 1.0481x over previous
#include <cuda_runtime.h>
#include <cstdint>

#define N_NODES 50000
#define N_EDGES 800000
#define N_GRAPHS 128
#define IN_CH 31
#define C_PAD 32
#define HID 64
#define EPS_IN 1e-5f

#define SCAN_B 1024
#define SCAN_NB ((N_NODES + SCAN_B - 1) / SCAN_B)  // 49

typedef unsigned long long u64;

// ---------------- scratch (static device globals; no allocation) ----------------
__device__ float g_xpad[N_NODES * C_PAD];
__device__ float g_bufA[N_NODES * HID];
__device__ float g_bufB[N_NODES * HID];
__device__ float g_aggr[N_NODES * HID];
__device__ int g_deg[N_NODES];
__device__ int g_rowptr[N_NODES + 1];
__device__ int g_fill[N_NODES];
__device__ int g_csr[N_EDGES];
__device__ int g_part[SCAN_NB];
__device__ unsigned g_hbits[N_GRAPHS * 3 * HID];
__device__ float g_Wl1T[(3 * HID) * (2 * HID)];
__device__ float g_Wl2T[(2 * HID) * (HID / 2)];

// ---------------- f32x2 packed helpers ----------------
__device__ __forceinline__ u64 pk2(float v) {
    u64 r;
    asm("mov.b64 %0, {%1, %1};" : "=l"(r) : "f"(v));
    return r;
}
__device__ __forceinline__ u64 ffma2(u64 a, u64 b, u64 c) {
    u64 d;
    asm("fma.rn.f32x2 %0, %1, %2, %3;" : "=l"(d) : "l"(a), "l"(b), "l"(c));
    return d;
}
__device__ __forceinline__ float2 up2(u64 v) {
    float2 f;
    asm("mov.b64 {%0, %1}, %2;" : "=f"(f.x), "=f"(f.y) : "l"(v));
    return f;
}

// ---------------- prep: zero deg/hbits, transpose head weights, pad x ----------------
__global__ void k_prep(const float* __restrict__ x,
                       const float* __restrict__ Wl1,
                       const float* __restrict__ Wl2) {
    int i = blockIdx.x * 256 + threadIdx.x;
    if (i < N_NODES * C_PAD) {
        int n = i >> 5, c = i & 31;
        g_xpad[i] = (c < IN_CH) ? x[n * IN_CH + c] : 0.f;
    }
    if (i < N_NODES) g_deg[i] = 0;
    if (i < N_GRAPHS * 3 * HID) g_hbits[i] = 0u;
    if (i < 128 * 192) {
        int o = i / 192, c = i % 192;
        g_Wl1T[c * 128 + o] = Wl1[i];
    }
    if (i < 32 * 128) {
        int o = i / 128, c = i % 128;
        g_Wl2T[c * 32 + o] = Wl2[i];
    }
}

// ---------------- CSR build ----------------
__global__ void k_hist(const int* __restrict__ dst) {
    int e4 = blockIdx.x * 256 + threadIdx.x;
    if (e4 < N_EDGES / 4) {
        int4 d = __ldg((const int4*)dst + e4);
        atomicAdd(&g_deg[d.x], 1);
        atomicAdd(&g_deg[d.y], 1);
        atomicAdd(&g_deg[d.z], 1);
        atomicAdd(&g_deg[d.w], 1);
    }
}

// block reduce via shfl
__global__ void k_scanA() {
    __shared__ int ws[32];
    int tid = threadIdx.x;
    int i = blockIdx.x * SCAN_B + tid;
    int v = (i < N_NODES) ? g_deg[i] : 0;
#pragma unroll
    for (int off = 16; off; off >>= 1) v += __shfl_xor_sync(0xFFFFFFFFu, v, off);
    if ((tid & 31) == 0) ws[tid >> 5] = v;
    __syncthreads();
    if (tid < 32) {
        int u = ws[tid];
#pragma unroll
        for (int off = 16; off; off >>= 1) u += __shfl_xor_sync(0xFFFFFFFFu, u, off);
        if (tid == 0) g_part[blockIdx.x] = u;
    }
}

// block scan (warp-shfl) with fused per-block offset (sums g_part[0..b-1])
__global__ void k_scanC() {
    __shared__ int wsum[32];
    __shared__ int soff_sh;
    int tid = threadIdx.x;
    int b = blockIdx.x;
    int lane = tid & 31, wid = tid >> 5;
    if (tid == 0) soff_sh = 0;
    __syncthreads();
    if (tid < 64) {
        int pv = (tid < b) ? g_part[tid] : 0;  // b <= 48 < 64
#pragma unroll
        for (int off = 16; off; off >>= 1) pv += __shfl_xor_sync(0xFFFFFFFFu, pv, off);
        if ((tid & 31) == 0) atomicAdd(&soff_sh, pv);
    }
    int i = b * SCAN_B + tid;
    int v = (i < N_NODES) ? g_deg[i] : 0;
    int sc = v;
#pragma unroll
    for (int off = 1; off < 32; off <<= 1) {
        int a = __shfl_up_sync(0xFFFFFFFFu, sc, off);
        if (lane >= off) sc += a;
    }
    if (lane == 31) wsum[wid] = sc;
    __syncthreads();
    if (tid < 32) {
        int u = wsum[tid];
#pragma unroll
        for (int off = 1; off < 32; off <<= 1) {
            int a = __shfl_up_sync(0xFFFFFFFFu, u, off);
            if (tid >= off) u += a;
        }
        wsum[tid] = u;
    }
    __syncthreads();
    int woff = (wid > 0) ? wsum[wid - 1] : 0;
    if (i < N_NODES) {
        int incl = sc + woff + soff_sh;
        g_rowptr[i + 1] = incl;
        g_fill[i] = incl - v;
    }
    if (b == 0 && tid == 0) g_rowptr[0] = 0;
}

__global__ void k_scatter(const int* __restrict__ src, const int* __restrict__ dst) {
    int e4 = blockIdx.x * 256 + threadIdx.x;
    if (e4 < N_EDGES / 4) {
        int4 d = __ldg((const int4*)dst + e4);
        int4 sv = __ldg((const int4*)src + e4);
        int p0 = atomicAdd(&g_fill[d.x], 1);
        int p1 = atomicAdd(&g_fill[d.y], 1);
        int p2 = atomicAdd(&g_fill[d.z], 1);
        int p3 = atomicAdd(&g_fill[d.w], 1);
        g_csr[p0] = sv.x;
        g_csr[p1] = sv.y;
        g_csr[p2] = sv.z;
        g_csr[p3] = sv.w;
    }
}

// ---------------- one-pass segment softmax aggregation ----------------
// aggr[n,c] = sum_e v*exp(t*v) / sum_e exp(t*v)  (shift-invariant; logits bounded)
// Proven structure; main loop unrolled x8 for deeper MLP, then x4, then scalar tail.
__global__ __launch_bounds__(256) void k_aggr32(const float* __restrict__ xin,
                                                const float* __restrict__ tptr,
                                                float* __restrict__ aggr) {
    int node = (blockIdx.x * 256 + threadIdx.x) >> 5;
    int lane = threadIdx.x & 31;
    if (node >= N_NODES) return;
    float t = __ldg(tptr);
    int beg = g_rowptr[node];
    int end = g_rowptr[node + 1];
    float num = 0.f, den = 0.f;
    int k = beg;
#define ACC1(v)                    \
    {                              \
        float e = __expf((v) * t); \
        den += e;                  \
        num += (v) * e;            \
    }
    for (; k + 8 <= end; k += 8) {
        int s0 = g_csr[k], s1 = g_csr[k + 1], s2 = g_csr[k + 2], s3 = g_csr[k + 3];
        int s4 = g_csr[k + 4], s5 = g_csr[k + 5], s6 = g_csr[k + 6], s7 = g_csr[k + 7];
        float v0 = xin[(size_t)s0 * C_PAD + lane];
        float v1 = xin[(size_t)s1 * C_PAD + lane];
        float v2 = xin[(size_t)s2 * C_PAD + lane];
        float v3 = xin[(size_t)s3 * C_PAD + lane];
        float v4 = xin[(size_t)s4 * C_PAD + lane];
        float v5 = xin[(size_t)s5 * C_PAD + lane];
        float v6 = xin[(size_t)s6 * C_PAD + lane];
        float v7 = xin[(size_t)s7 * C_PAD + lane];
        ACC1(v0) ACC1(v1) ACC1(v2) ACC1(v3) ACC1(v4) ACC1(v5) ACC1(v6) ACC1(v7)
    }
    for (; k + 4 <= end; k += 4) {
        int s0 = g_csr[k], s1 = g_csr[k + 1], s2 = g_csr[k + 2], s3 = g_csr[k + 3];
        float v0 = xin[(size_t)s0 * C_PAD + lane];
        float v1 = xin[(size_t)s1 * C_PAD + lane];
        float v2 = xin[(size_t)s2 * C_PAD + lane];
        float v3 = xin[(size_t)s3 * C_PAD + lane];
        ACC1(v0) ACC1(v1) ACC1(v2) ACC1(v3)
    }
    for (; k < end; k++) {
        float v = xin[(size_t)g_csr[k] * C_PAD + lane];
        ACC1(v)
    }
#undef ACC1
    aggr[(size_t)node * C_PAD + lane] = (den > 0.f) ? num / den : 0.f;
}

__global__ __launch_bounds__(256) void k_aggr64(const float* __restrict__ xin,
                                                const float* __restrict__ tptr,
                                                float* __restrict__ aggr) {
    int node = (blockIdx.x * 256 + threadIdx.x) >> 5;
    int lane = threadIdx.x & 31;
    if (node >= N_NODES) return;
    float t = __ldg(tptr);
    int beg = g_rowptr[node];
    int end = g_rowptr[node + 1];
    float nx = 0.f, ny = 0.f, dx = 0.f, dy = 0.f;
    int co = 2 * lane;
    int k = beg;
#define ACC2(v)                       \
    {                                 \
        float e0 = __expf((v).x * t); \
        float e1 = __expf((v).y * t); \
        dx += e0;                     \
        nx += (v).x * e0;             \
        dy += e1;                     \
        ny += (v).y * e1;             \
    }
    for (; k + 8 <= end; k += 8) {
        int s0 = g_csr[k], s1 = g_csr[k + 1], s2 = g_csr[k + 2], s3 = g_csr[k + 3];
        int s4 = g_csr[k + 4], s5 = g_csr[k + 5], s6 = g_csr[k + 6], s7 = g_csr[k + 7];
        float2 v0 = *(const float2*)(xin + (size_t)s0 * HID + co);
        float2 v1 = *(const float2*)(xin + (size_t)s1 * HID + co);
        float2 v2 = *(const float2*)(xin + (size_t)s2 * HID + co);
        float2 v3 = *(const float2*)(xin + (size_t)s3 * HID + co);
        float2 v4 = *(const float2*)(xin + (size_t)s4 * HID + co);
        float2 v5 = *(const float2*)(xin + (size_t)s5 * HID + co);
        float2 v6 = *(const float2*)(xin + (size_t)s6 * HID + co);
        float2 v7 = *(const float2*)(xin + (size_t)s7 * HID + co);
        ACC2(v0) ACC2(v1) ACC2(v2) ACC2(v3) ACC2(v4) ACC2(v5) ACC2(v6) ACC2(v7)
    }
    for (; k + 4 <= end; k += 4) {
        int s0 = g_csr[k], s1 = g_csr[k + 1], s2 = g_csr[k + 2], s3 = g_csr[k + 3];
        float2 v0 = *(const float2*)(xin + (size_t)s0 * HID + co);
        float2 v1 = *(const float2*)(xin + (size_t)s1 * HID + co);
        float2 v2 = *(const float2*)(xin + (size_t)s2 * HID + co);
        float2 v3 = *(const float2*)(xin + (size_t)s3 * HID + co);
        ACC2(v0) ACC2(v1) ACC2(v2) ACC2(v3)
    }
    for (; k < end; k++) {
        int s = g_csr[k];
        float2 v = *(const float2*)(xin + (size_t)s * HID + co);
        ACC2(v)
    }
#undef ACC2
    float2 o;
    o.x = (dx > 0.f) ? nx / dx : 0.f;
    o.y = (dy > 0.f) ? ny / dy : 0.f;
    *(float2*)(aggr + (size_t)node * HID + co) = o;
}

// ---------------- fused dual-GEMM + instance-norm + relu + per-graph segmax -----------
// PROVEN round-9 form: 16 o-quads x 16 node-groups of 8 nodes, pk2+ffma2 mainloop,
// batched segmax epilogue.
template <int C, int CREAL>
__global__ __launch_bounds__(256) void k_lin(const float* __restrict__ xin,
                                             const float* __restrict__ aggr,
                                             const float* __restrict__ Wr,
                                             const float* __restrict__ br,
                                             const float* __restrict__ Ws,
                                             const int* __restrict__ batch,
                                             int loff,
                                             float* __restrict__ y) {
    __shared__ __align__(16) float sWr[C * HID];  // [c][o]
    __shared__ __align__(16) float sWs[C * HID];  // [c][o]
    __shared__ __align__(16) float sb[HID];
    int tid = threadIdx.x;
    for (int i = tid; i < C * HID; i += 256) {
        int o = i / C, c = i % C;
        float wr = (c < CREAL) ? Wr[o * CREAL + c] : 0.f;
        float ws = (c < CREAL) ? Ws[o * CREAL + c] : 0.f;
        sWr[c * HID + o] = wr;
        sWs[c * HID + o] = ws;
    }
    if (tid < HID) sb[tid] = br[tid];
    __syncthreads();

    int oq = tid & 15;
    int ng = tid >> 4;
    int o0 = oq * 4;
    int n0 = blockIdx.x * 128 + ng * 8;

    size_t rowoff[8];
#pragma unroll
    for (int n = 0; n < 8; n++) {
        int node = n0 + n;
        if (node >= N_NODES) node = N_NODES - 1;
        rowoff[n] = (size_t)node * C;
    }

    ulonglong2 b2 = *(const ulonglong2*)&sb[o0];
    u64 accA[8], accB[8];
#pragma unroll
    for (int n = 0; n < 8; n++) { accA[n] = b2.x; accB[n] = b2.y; }

    for (int c = 0; c < C; c += 4) {
        ulonglong2 wr0 = *(const ulonglong2*)&sWr[(c + 0) * HID + o0];
        ulonglong2 wr1 = *(const ulonglong2*)&sWr[(c + 1) * HID + o0];
        ulonglong2 wr2 = *(const ulonglong2*)&sWr[(c + 2) * HID + o0];
        ulonglong2 wr3 = *(const ulonglong2*)&sWr[(c + 3) * HID + o0];
        ulonglong2 ws0 = *(const ulonglong2*)&sWs[(c + 0) * HID + o0];
        ulonglong2 ws1 = *(const ulonglong2*)&sWs[(c + 1) * HID + o0];
        ulonglong2 ws2 = *(const ulonglong2*)&sWs[(c + 2) * HID + o0];
        ulonglong2 ws3 = *(const ulonglong2*)&sWs[(c + 3) * HID + o0];
#pragma unroll
        for (int n = 0; n < 8; n++) {
            float4 av = *(const float4*)(aggr + rowoff[n] + c);
            float4 xv = *(const float4*)(xin + rowoff[n] + c);
            u64 p;
            p = pk2(av.x); accA[n] = ffma2(p, wr0.x, accA[n]); accB[n] = ffma2(p, wr0.y, accB[n]);
            p = pk2(xv.x); accA[n] = ffma2(p, ws0.x, accA[n]); accB[n] = ffma2(p, ws0.y, accB[n]);
            p = pk2(av.y); accA[n] = ffma2(p, wr1.x, accA[n]); accB[n] = ffma2(p, wr1.y, accB[n]);
            p = pk2(xv.y); accA[n] = ffma2(p, ws1.x, accA[n]); accB[n] = ffma2(p, ws1.y, accB[n]);
            p = pk2(av.z); accA[n] = ffma2(p, wr2.x, accA[n]); accB[n] = ffma2(p, wr2.y, accB[n]);
            p = pk2(xv.z); accA[n] = ffma2(p, ws2.x, accA[n]); accB[n] = ffma2(p, ws2.y, accB[n]);
            p = pk2(av.w); accA[n] = ffma2(p, wr3.x, accA[n]); accB[n] = ffma2(p, wr3.y, accB[n]);
            p = pk2(xv.w); accA[n] = ffma2(p, ws3.x, accA[n]); accB[n] = ffma2(p, ws3.y, accB[n]);
        }
    }

    // epilogue: instance norm (16-lane group) + relu + store + batched segmax
    float4 gm = make_float4(0.f, 0.f, 0.f, 0.f);
    int curg = -1;
#pragma unroll
    for (int n = 0; n < 8; n++) {
        int node = n0 + n;
        if (node >= N_NODES) break;  // uniform across the 16-lane group
        float2 p0 = up2(accA[n]);
        float2 p1 = up2(accB[n]);
        float sum = p0.x + p0.y + p1.x + p1.y;
#pragma unroll
        for (int off = 8; off; off >>= 1) sum += __shfl_xor_sync(0xFFFFFFFFu, sum, off);
        float mu = sum * (1.0f / HID);
        float d0 = p0.x - mu, d1 = p0.y - mu, d2 = p1.x - mu, d3 = p1.y - mu;
        float q = d0 * d0 + d1 * d1 + d2 * d2 + d3 * d3;
#pragma unroll
        for (int off = 8; off; off >>= 1) q += __shfl_xor_sync(0xFFFFFFFFu, q, off);
        float r = rsqrtf(q * (1.0f / HID) + EPS_IN);
        float4 o;
        o.x = fmaxf(d0 * r, 0.f);
        o.y = fmaxf(d1 * r, 0.f);
        o.z = fmaxf(d2 * r, 0.f);
        o.w = fmaxf(d3 * r, 0.f);
        *(float4*)&y[(size_t)node * HID + o0] = o;
        int g = __ldg(&batch[node]);
        if (g != curg) {
            if (curg >= 0) {
                unsigned* hrow = g_hbits + curg * (3 * HID) + loff + o0;
                atomicMax(&hrow[0], __float_as_uint(gm.x));
                atomicMax(&hrow[1], __float_as_uint(gm.y));
                atomicMax(&hrow[2], __float_as_uint(gm.z));
                atomicMax(&hrow[3], __float_as_uint(gm.w));
            }
            curg = g;
            gm = o;
        } else {
            gm.x = fmaxf(gm.x, o.x);
            gm.y = fmaxf(gm.y, o.y);
            gm.z = fmaxf(gm.z, o.z);
            gm.w = fmaxf(gm.w, o.w);
        }
    }
    if (curg >= 0) {
        unsigned* hrow = g_hbits + curg * (3 * HID) + loff + o0;
        atomicMax(&hrow[0], __float_as_uint(gm.x));
        atomicMax(&hrow[1], __float_as_uint(gm.y));
        atomicMax(&hrow[2], __float_as_uint(gm.z));
        atomicMax(&hrow[3], __float_as_uint(gm.w));
    }
}

// ---------------- head MLP: one block per graph ----------------
__global__ __launch_bounds__(192) void k_final(const float* __restrict__ bl1,
                                               const float* __restrict__ bl2,
                                               float* __restrict__ out) {
    __shared__ float sh[3 * HID];
    __shared__ float sz1[2 * HID];
    __shared__ float sz2[HID / 2];
    int g = blockIdx.x;
    int tid = threadIdx.x;
    sh[tid] = __uint_as_float(g_hbits[g * (3 * HID) + tid]);
    __syncthreads();
    if (tid < 2 * HID) {
        float acc = bl1[tid];
#pragma unroll 4
        for (int c = 0; c < 3 * HID; c++) acc += sh[c] * g_Wl1T[c * (2 * HID) + tid];
        sz1[tid] = fmaxf(acc, 0.f);
    }
    __syncthreads();
    if (tid < HID / 2) {
        float acc = bl2[tid];
#pragma unroll 4
        for (int c = 0; c < 2 * HID; c++) acc += sz1[c] * g_Wl2T[c * (HID / 2) + tid];
        sz2[tid] = acc;
    }
    __syncthreads();
    if (tid < 32) {
        float v = sz2[tid];
        float q = v * v;
#pragma unroll
        for (int o = 16; o; o >>= 1) q += __shfl_xor_sync(0xFFFFFFFFu, q, o);
        float nrm = fmaxf(sqrtf(q), 1e-12f);
        out[g * 32 + tid] = v / nrm;
    }
}

// ---------------- launch ----------------
extern "C" void kernel_launch(void* const* d_in, const int* in_sizes, int n_in,
                              void* d_out, int out_size) {
    const float* x = (const float*)d_in[0];
    const int* ei = (const int*)d_in[1];
    const int* src = ei;
    const int* dst = ei + N_EDGES;
    const int* batch = (const int*)d_in[2];
    const float* t = (const float*)d_in[3];
    const float* W1r = (const float*)d_in[4];
    const float* b1 = (const float*)d_in[5];
    const float* W1s = (const float*)d_in[6];
    const float* W2r = (const float*)d_in[7];
    const float* b2 = (const float*)d_in[8];
    const float* W2s = (const float*)d_in[9];
    const float* W3r = (const float*)d_in[10];
    const float* b3 = (const float*)d_in[11];
    const float* W3s = (const float*)d_in[12];
    const float* Wl1 = (const float*)d_in[13];
    const float* bl1 = (const float*)d_in[14];
    const float* Wl2 = (const float*)d_in[15];
    const float* bl2 = (const float*)d_in[16];
    float* out = (float*)d_out;

    float *xpad, *bufA, *bufB, *aggr;
    cudaGetSymbolAddress((void**)&xpad, g_xpad);
    cudaGetSymbolAddress((void**)&bufA, g_bufA);
    cudaGetSymbolAddress((void**)&bufB, g_bufB);
    cudaGetSymbolAddress((void**)&aggr, g_aggr);

    const int PB = (N_NODES * C_PAD + 255) / 256;  // 6250
    const int E4B = (N_EDGES / 4 + 255) / 256;     // 782
    const int WB = (N_NODES * 32 + 255) / 256;     // warp-per-node: 6250
    const int LB = (N_NODES + 127) / 128;          // 391

    k_prep<<<PB, 256>>>(x, Wl1, Wl2);
    k_hist<<<E4B, 256>>>(dst);
    k_scanA<<<SCAN_NB, SCAN_B>>>();
    k_scanC<<<SCAN_NB, SCAN_B>>>();
    k_scatter<<<E4B, 256>>>(src, dst);

    // layer 1 (padded to 32 ch; channel 31 is exactly zero everywhere)
    k_aggr32<<<WB, 256>>>(xpad, t, aggr);
    k_lin<C_PAD, IN_CH><<<LB, 256>>>(xpad, aggr, W1r, b1, W1s, batch, 0, bufA);

    // layer 2
    k_aggr64<<<WB, 256>>>(bufA, t, aggr);
    k_lin<HID, HID><<<LB, 256>>>(bufA, aggr, W2r, b2, W2s, batch, HID, bufB);

    // layer 3
    k_aggr64<<<WB, 256>>>(bufB, t, aggr);
    k_lin<HID, HID><<<LB, 256>>>(bufB, aggr, W3r, b3, W3s, batch, 2 * HID, bufA);

    k_final<<<N_GRAPHS, 192>>>(bl1, bl2, out);
    (void)in_sizes; (void)n_in; (void)out_size;
}

// round 11
// speedup vs baseline: 1.4319x; 1.0184x over previous
#include <cuda_runtime.h>
#include <cstdint>

#define N_NODES 50000
#define N_EDGES 800000
#define N_GRAPHS 128
#define IN_CH 31
#define C_PAD 32
#define HID 64
#define EPS_IN 1e-5f

#define SCAN_B 1024
#define SCAN_NB ((N_NODES + SCAN_B - 1) / SCAN_B)  // 49

typedef unsigned long long u64;

// ---------------- scratch (static device globals; no allocation) ----------------
// INVARIANT: g_deg is all-zero at every kernel_launch entry (zero-init at module
// load; k_scan re-zeroes it after consuming it each run). g_syncc is zeroed by
// k_prep before k_scan uses it.
__device__ float g_xpad[N_NODES * C_PAD];
__device__ float g_bufA[N_NODES * HID];
__device__ float g_bufB[N_NODES * HID];
__device__ float g_aggr[N_NODES * HID];
__device__ int g_deg[N_NODES];
__device__ int g_rowptr[N_NODES + 1];
__device__ int g_fill[N_NODES];
__device__ int g_csr[N_EDGES];
__device__ int g_part[SCAN_NB];
__device__ int g_syncc;
__device__ unsigned g_hbits[N_GRAPHS * 3 * HID];
__device__ float g_Wl1T[(3 * HID) * (2 * HID)];
__device__ float g_Wl2T[(2 * HID) * (HID / 2)];

// ---------------- f32x2 packed helpers ----------------
__device__ __forceinline__ u64 pk2(float v) {
    u64 r;
    asm("mov.b64 %0, {%1, %1};" : "=l"(r) : "f"(v));
    return r;
}
__device__ __forceinline__ u64 ffma2(u64 a, u64 b, u64 c) {
    u64 d;
    asm("fma.rn.f32x2 %0, %1, %2, %3;" : "=l"(d) : "l"(a), "l"(b), "l"(c));
    return d;
}
__device__ __forceinline__ float2 up2(u64 v) {
    float2 f;
    asm("mov.b64 {%0, %1}, %2;" : "=f"(f.x), "=f"(f.y) : "l"(v));
    return f;
}

// ---------------- prep: pad x, zero hbits/sync, transpose head weights, AND hist ----
// g_deg is guaranteed zero at entry (see invariant above), so the degree
// histogram runs here, overlapped with the xpad streaming stores.
__global__ void k_prep(const float* __restrict__ x,
                       const float* __restrict__ Wl1,
                       const float* __restrict__ Wl2,
                       const int* __restrict__ dst) {
    int i = blockIdx.x * 256 + threadIdx.x;
    if (i == 0) g_syncc = 0;
    if (i < N_NODES * C_PAD) {
        int n = i >> 5, c = i & 31;
        g_xpad[i] = (c < IN_CH) ? x[n * IN_CH + c] : 0.f;
    }
    if (i < N_GRAPHS * 3 * HID) g_hbits[i] = 0u;
    if (i < 128 * 192) {
        int o = i / 192, c = i % 192;
        g_Wl1T[c * 128 + o] = Wl1[i];
    }
    if (i < 32 * 128) {
        int o = i / 128, c = i % 128;
        g_Wl2T[c * 32 + o] = Wl2[i];
    }
    if (i < N_EDGES / 4) {
        int4 d = __ldg((const int4*)dst + i);
        atomicAdd(&g_deg[d.x], 1);
        atomicAdd(&g_deg[d.y], 1);
        atomicAdd(&g_deg[d.z], 1);
        atomicAdd(&g_deg[d.w], 1);
    }
}

// ---------------- single-kernel exclusive scan with software global barrier --------
// 49 blocks x 1024 threads: always co-resident on 148 SMs -> spin is safe.
// Phase A: block sums -> g_part. Barrier. Phase B: per-block offset.
// Phase C: warp-shfl block scan -> g_rowptr / g_fill; re-zero g_deg for next run.
__global__ void k_scan() {
    __shared__ int ws[32];
    __shared__ int soff_sh;
    int tid = threadIdx.x;
    int b = blockIdx.x;
    int lane = tid & 31, w = tid >> 5;
    int i = b * SCAN_B + tid;
    int v = (i < N_NODES) ? g_deg[i] : 0;

    // phase A: block reduce
    int r = v;
#pragma unroll
    for (int off = 16; off; off >>= 1) r += __shfl_xor_sync(0xFFFFFFFFu, r, off);
    if (lane == 0) ws[w] = r;
    __syncthreads();
    if (tid < 32) {
        int u = ws[tid];
#pragma unroll
        for (int off = 16; off; off >>= 1) u += __shfl_xor_sync(0xFFFFFFFFu, u, off);
        if (tid == 0) {
            g_part[b] = u;
            __threadfence();
            atomicAdd(&g_syncc, 1);
        }
    }
    if (tid == 0) soff_sh = 0;
    // global barrier
    if (tid == 0) {
        while (*(volatile int*)&g_syncc < SCAN_NB) {}
    }
    __syncthreads();
    __threadfence();

    // phase B: sum of g_part[0..b-1]
    if (tid < 64) {
        int pv = (tid < b) ? g_part[tid] : 0;  // b <= 48 < 64
#pragma unroll
        for (int off = 16; off; off >>= 1) pv += __shfl_xor_sync(0xFFFFFFFFu, pv, off);
        if (lane == 0) atomicAdd(&soff_sh, pv);
    }

    // phase C: block scan (warp shfl)
    int sc = v;
#pragma unroll
    for (int off = 1; off < 32; off <<= 1) {
        int a = __shfl_up_sync(0xFFFFFFFFu, sc, off);
        if (lane >= off) sc += a;
    }
    if (lane == 31) ws[w] = sc;
    __syncthreads();
    if (tid < 32) {
        int u = ws[tid];
#pragma unroll
        for (int off = 1; off < 32; off <<= 1) {
            int a = __shfl_up_sync(0xFFFFFFFFu, u, off);
            if (tid >= off) u += a;
        }
        ws[tid] = u;
    }
    __syncthreads();
    int woff = (w > 0) ? ws[w - 1] : 0;
    if (i < N_NODES) {
        int incl = sc + woff + soff_sh;
        g_rowptr[i + 1] = incl;
        g_fill[i] = incl - v;
        g_deg[i] = 0;  // restore invariant for next run's fused hist
    }
    if (b == 0 && tid == 0) g_rowptr[0] = 0;
}

__global__ void k_scatter(const int* __restrict__ src, const int* __restrict__ dst) {
    int e4 = blockIdx.x * 256 + threadIdx.x;
    if (e4 < N_EDGES / 4) {
        int4 d = __ldg((const int4*)dst + e4);
        int4 sv = __ldg((const int4*)src + e4);
        int p0 = atomicAdd(&g_fill[d.x], 1);
        int p1 = atomicAdd(&g_fill[d.y], 1);
        int p2 = atomicAdd(&g_fill[d.z], 1);
        int p3 = atomicAdd(&g_fill[d.w], 1);
        g_csr[p0] = sv.x;
        g_csr[p1] = sv.y;
        g_csr[p2] = sv.z;
        g_csr[p3] = sv.w;
    }
}

// ---------------- one-pass segment softmax aggregation ----------------
// aggr[n,c] = sum_e v*exp(t*v) / sum_e exp(t*v)  (shift-invariant; logits bounded)
__global__ __launch_bounds__(256) void k_aggr32(const float* __restrict__ xin,
                                                const float* __restrict__ tptr,
                                                float* __restrict__ aggr) {
    int node = (blockIdx.x * 256 + threadIdx.x) >> 5;
    int lane = threadIdx.x & 31;
    if (node >= N_NODES) return;
    float t = __ldg(tptr);
    int beg = g_rowptr[node];
    int end = g_rowptr[node + 1];
    float num = 0.f, den = 0.f;
    int k = beg;
#define ACC1(v)                    \
    {                              \
        float e = __expf((v) * t); \
        den += e;                  \
        num += (v) * e;            \
    }
    for (; k + 8 <= end; k += 8) {
        int s0 = g_csr[k], s1 = g_csr[k + 1], s2 = g_csr[k + 2], s3 = g_csr[k + 3];
        int s4 = g_csr[k + 4], s5 = g_csr[k + 5], s6 = g_csr[k + 6], s7 = g_csr[k + 7];
        float v0 = xin[(size_t)s0 * C_PAD + lane];
        float v1 = xin[(size_t)s1 * C_PAD + lane];
        float v2 = xin[(size_t)s2 * C_PAD + lane];
        float v3 = xin[(size_t)s3 * C_PAD + lane];
        float v4 = xin[(size_t)s4 * C_PAD + lane];
        float v5 = xin[(size_t)s5 * C_PAD + lane];
        float v6 = xin[(size_t)s6 * C_PAD + lane];
        float v7 = xin[(size_t)s7 * C_PAD + lane];
        ACC1(v0) ACC1(v1) ACC1(v2) ACC1(v3) ACC1(v4) ACC1(v5) ACC1(v6) ACC1(v7)
    }
    for (; k + 4 <= end; k += 4) {
        int s0 = g_csr[k], s1 = g_csr[k + 1], s2 = g_csr[k + 2], s3 = g_csr[k + 3];
        float v0 = xin[(size_t)s0 * C_PAD + lane];
        float v1 = xin[(size_t)s1 * C_PAD + lane];
        float v2 = xin[(size_t)s2 * C_PAD + lane];
        float v3 = xin[(size_t)s3 * C_PAD + lane];
        ACC1(v0) ACC1(v1) ACC1(v2) ACC1(v3)
    }
    for (; k < end; k++) {
        float v = xin[(size_t)g_csr[k] * C_PAD + lane];
        ACC1(v)
    }
#undef ACC1
    aggr[(size_t)node * C_PAD + lane] = (den > 0.f) ? num / den : 0.f;
}

__global__ __launch_bounds__(256) void k_aggr64(const float* __restrict__ xin,
                                                const float* __restrict__ tptr,
                                                float* __restrict__ aggr) {
    int node = (blockIdx.x * 256 + threadIdx.x) >> 5;
    int lane = threadIdx.x & 31;
    if (node >= N_NODES) return;
    float t = __ldg(tptr);
    int beg = g_rowptr[node];
    int end = g_rowptr[node + 1];
    float nx = 0.f, ny = 0.f, dx = 0.f, dy = 0.f;
    int co = 2 * lane;
    int k = beg;
#define ACC2(v)                       \
    {                                 \
        float e0 = __expf((v).x * t); \
        float e1 = __expf((v).y * t); \
        dx += e0;                     \
        nx += (v).x * e0;             \
        dy += e1;                     \
        ny += (v).y * e1;             \
    }
    for (; k + 8 <= end; k += 8) {
        int s0 = g_csr[k], s1 = g_csr[k + 1], s2 = g_csr[k + 2], s3 = g_csr[k + 3];
        int s4 = g_csr[k + 4], s5 = g_csr[k + 5], s6 = g_csr[k + 6], s7 = g_csr[k + 7];
        float2 v0 = *(const float2*)(xin + (size_t)s0 * HID + co);
        float2 v1 = *(const float2*)(xin + (size_t)s1 * HID + co);
        float2 v2 = *(const float2*)(xin + (size_t)s2 * HID + co);
        float2 v3 = *(const float2*)(xin + (size_t)s3 * HID + co);
        float2 v4 = *(const float2*)(xin + (size_t)s4 * HID + co);
        float2 v5 = *(const float2*)(xin + (size_t)s5 * HID + co);
        float2 v6 = *(const float2*)(xin + (size_t)s6 * HID + co);
        float2 v7 = *(const float2*)(xin + (size_t)s7 * HID + co);
        ACC2(v0) ACC2(v1) ACC2(v2) ACC2(v3) ACC2(v4) ACC2(v5) ACC2(v6) ACC2(v7)
    }
    for (; k + 4 <= end; k += 4) {
        int s0 = g_csr[k], s1 = g_csr[k + 1], s2 = g_csr[k + 2], s3 = g_csr[k + 3];
        float2 v0 = *(const float2*)(xin + (size_t)s0 * HID + co);
        float2 v1 = *(const float2*)(xin + (size_t)s1 * HID + co);
        float2 v2 = *(const float2*)(xin + (size_t)s2 * HID + co);
        float2 v3 = *(const float2*)(xin + (size_t)s3 * HID + co);
        ACC2(v0) ACC2(v1) ACC2(v2) ACC2(v3)
    }
    for (; k < end; k++) {
        int s = g_csr[k];
        float2 v = *(const float2*)(xin + (size_t)s * HID + co);
        ACC2(v)
    }
#undef ACC2
    float2 o;
    o.x = (dx > 0.f) ? nx / dx : 0.f;
    o.y = (dy > 0.f) ? ny / dy : 0.f;
    *(float2*)(aggr + (size_t)node * HID + co) = o;
}

// ---------------- fused dual-GEMM + instance-norm + relu + per-graph segmax -----------
// PROVEN form: 16 o-quads x 16 node-groups of 8 nodes, pk2+ffma2 mainloop,
// batched segmax epilogue.
template <int C, int CREAL>
__global__ __launch_bounds__(256) void k_lin(const float* __restrict__ xin,
                                             const float* __restrict__ aggr,
                                             const float* __restrict__ Wr,
                                             const float* __restrict__ br,
                                             const float* __restrict__ Ws,
                                             const int* __restrict__ batch,
                                             int loff,
                                             float* __restrict__ y) {
    __shared__ __align__(16) float sWr[C * HID];  // [c][o]
    __shared__ __align__(16) float sWs[C * HID];  // [c][o]
    __shared__ __align__(16) float sb[HID];
    int tid = threadIdx.x;
    for (int i = tid; i < C * HID; i += 256) {
        int o = i / C, c = i % C;
        float wr = (c < CREAL) ? Wr[o * CREAL + c] : 0.f;
        float ws = (c < CREAL) ? Ws[o * CREAL + c] : 0.f;
        sWr[c * HID + o] = wr;
        sWs[c * HID + o] = ws;
    }
    if (tid < HID) sb[tid] = br[tid];
    __syncthreads();

    int oq = tid & 15;
    int ng = tid >> 4;
    int o0 = oq * 4;
    int n0 = blockIdx.x * 128 + ng * 8;

    size_t rowoff[8];
#pragma unroll
    for (int n = 0; n < 8; n++) {
        int node = n0 + n;
        if (node >= N_NODES) node = N_NODES - 1;
        rowoff[n] = (size_t)node * C;
    }

    ulonglong2 b2 = *(const ulonglong2*)&sb[o0];
    u64 accA[8], accB[8];
#pragma unroll
    for (int n = 0; n < 8; n++) { accA[n] = b2.x; accB[n] = b2.y; }

    for (int c = 0; c < C; c += 4) {
        ulonglong2 wr0 = *(const ulonglong2*)&sWr[(c + 0) * HID + o0];
        ulonglong2 wr1 = *(const ulonglong2*)&sWr[(c + 1) * HID + o0];
        ulonglong2 wr2 = *(const ulonglong2*)&sWr[(c + 2) * HID + o0];
        ulonglong2 wr3 = *(const ulonglong2*)&sWr[(c + 3) * HID + o0];
        ulonglong2 ws0 = *(const ulonglong2*)&sWs[(c + 0) * HID + o0];
        ulonglong2 ws1 = *(const ulonglong2*)&sWs[(c + 1) * HID + o0];
        ulonglong2 ws2 = *(const ulonglong2*)&sWs[(c + 2) * HID + o0];
        ulonglong2 ws3 = *(const ulonglong2*)&sWs[(c + 3) * HID + o0];
#pragma unroll
        for (int n = 0; n < 8; n++) {
            float4 av = *(const float4*)(aggr + rowoff[n] + c);
            float4 xv = *(const float4*)(xin + rowoff[n] + c);
            u64 p;
            p = pk2(av.x); accA[n] = ffma2(p, wr0.x, accA[n]); accB[n] = ffma2(p, wr0.y, accB[n]);
            p = pk2(xv.x); accA[n] = ffma2(p, ws0.x, accA[n]); accB[n] = ffma2(p, ws0.y, accB[n]);
            p = pk2(av.y); accA[n] = ffma2(p, wr1.x, accA[n]); accB[n] = ffma2(p, wr1.y, accB[n]);
            p = pk2(xv.y); accA[n] = ffma2(p, ws1.x, accA[n]); accB[n] = ffma2(p, ws1.y, accB[n]);
            p = pk2(av.z); accA[n] = ffma2(p, wr2.x, accA[n]); accB[n] = ffma2(p, wr2.y, accB[n]);
            p = pk2(xv.z); accA[n] = ffma2(p, ws2.x, accA[n]); accB[n] = ffma2(p, ws2.y, accB[n]);
            p = pk2(av.w); accA[n] = ffma2(p, wr3.x, accA[n]); accB[n] = ffma2(p, wr3.y, accB[n]);
            p = pk2(xv.w); accA[n] = ffma2(p, ws3.x, accA[n]); accB[n] = ffma2(p, ws3.y, accB[n]);
        }
    }

    // epilogue: instance norm (16-lane group) + relu + store + batched segmax
    float4 gm = make_float4(0.f, 0.f, 0.f, 0.f);
    int curg = -1;
#pragma unroll
    for (int n = 0; n < 8; n++) {
        int node = n0 + n;
        if (node >= N_NODES) break;  // uniform across the 16-lane group
        float2 p0 = up2(accA[n]);
        float2 p1 = up2(accB[n]);
        float sum = p0.x + p0.y + p1.x + p1.y;
#pragma unroll
        for (int off = 8; off; off >>= 1) sum += __shfl_xor_sync(0xFFFFFFFFu, sum, off);
        float mu = sum * (1.0f / HID);
        float d0 = p0.x - mu, d1 = p0.y - mu, d2 = p1.x - mu, d3 = p1.y - mu;
        float q = d0 * d0 + d1 * d1 + d2 * d2 + d3 * d3;
#pragma unroll
        for (int off = 8; off; off >>= 1) q += __shfl_xor_sync(0xFFFFFFFFu, q, off);
        float r = rsqrtf(q * (1.0f / HID) + EPS_IN);
        float4 o;
        o.x = fmaxf(d0 * r, 0.f);
        o.y = fmaxf(d1 * r, 0.f);
        o.z = fmaxf(d2 * r, 0.f);
        o.w = fmaxf(d3 * r, 0.f);
        *(float4*)&y[(size_t)node * HID + o0] = o;
        int g = __ldg(&batch[node]);
        if (g != curg) {
            if (curg >= 0) {
                unsigned* hrow = g_hbits + curg * (3 * HID) + loff + o0;
                atomicMax(&hrow[0], __float_as_uint(gm.x));
                atomicMax(&hrow[1], __float_as_uint(gm.y));
                atomicMax(&hrow[2], __float_as_uint(gm.z));
                atomicMax(&hrow[3], __float_as_uint(gm.w));
            }
            curg = g;
            gm = o;
        } else {
            gm.x = fmaxf(gm.x, o.x);
            gm.y = fmaxf(gm.y, o.y);
            gm.z = fmaxf(gm.z, o.z);
            gm.w = fmaxf(gm.w, o.w);
        }
    }
    if (curg >= 0) {
        unsigned* hrow = g_hbits + curg * (3 * HID) + loff + o0;
        atomicMax(&hrow[0], __float_as_uint(gm.x));
        atomicMax(&hrow[1], __float_as_uint(gm.y));
        atomicMax(&hrow[2], __float_as_uint(gm.z));
        atomicMax(&hrow[3], __float_as_uint(gm.w));
    }
}

// ---------------- head MLP: one block per graph ----------------
__global__ __launch_bounds__(192) void k_final(const float* __restrict__ bl1,
                                               const float* __restrict__ bl2,
                                               float* __restrict__ out) {
    __shared__ float sh[3 * HID];
    __shared__ float sz1[2 * HID];
    __shared__ float sz2[HID / 2];
    int g = blockIdx.x;
    int tid = threadIdx.x;
    sh[tid] = __uint_as_float(g_hbits[g * (3 * HID) + tid]);
    __syncthreads();
    if (tid < 2 * HID) {
        float acc = bl1[tid];
#pragma unroll 4
        for (int c = 0; c < 3 * HID; c++) acc += sh[c] * g_Wl1T[c * (2 * HID) + tid];
        sz1[tid] = fmaxf(acc, 0.f);
    }
    __syncthreads();
    if (tid < HID / 2) {
        float acc = bl2[tid];
#pragma unroll 4
        for (int c = 0; c < 2 * HID; c++) acc += sz1[c] * g_Wl2T[c * (HID / 2) + tid];
        sz2[tid] = acc;
    }
    __syncthreads();
    if (tid < 32) {
        float v = sz2[tid];
        float q = v * v;
#pragma unroll
        for (int o = 16; o; o >>= 1) q += __shfl_xor_sync(0xFFFFFFFFu, q, o);
        float nrm = fmaxf(sqrtf(q), 1e-12f);
        out[g * 32 + tid] = v / nrm;
    }
}

// ---------------- launch ----------------
extern "C" void kernel_launch(void* const* d_in, const int* in_sizes, int n_in,
                              void* d_out, int out_size) {
    const float* x = (const float*)d_in[0];
    const int* ei = (const int*)d_in[1];
    const int* src = ei;
    const int* dst = ei + N_EDGES;
    const int* batch = (const int*)d_in[2];
    const float* t = (const float*)d_in[3];
    const float* W1r = (const float*)d_in[4];
    const float* b1 = (const float*)d_in[5];
    const float* W1s = (const float*)d_in[6];
    const float* W2r = (const float*)d_in[7];
    const float* b2 = (const float*)d_in[8];
    const float* W2s = (const float*)d_in[9];
    const float* W3r = (const float*)d_in[10];
    const float* b3 = (const float*)d_in[11];
    const float* W3s = (const float*)d_in[12];
    const float* Wl1 = (const float*)d_in[13];
    const float* bl1 = (const float*)d_in[14];
    const float* Wl2 = (const float*)d_in[15];
    const float* bl2 = (const float*)d_in[16];
    float* out = (float*)d_out;

    float *xpad, *bufA, *bufB, *aggr;
    cudaGetSymbolAddress((void**)&xpad, g_xpad);
    cudaGetSymbolAddress((void**)&bufA, g_bufA);
    cudaGetSymbolAddress((void**)&bufB, g_bufB);
    cudaGetSymbolAddress((void**)&aggr, g_aggr);

    const int PB = (N_NODES * C_PAD + 255) / 256;  // 6250 (covers hist range too)
    const int E4B = (N_EDGES / 4 + 255) / 256;     // 782
    const int WB = (N_NODES * 32 + 255) / 256;     // warp-per-node: 6250
    const int LB = (N_NODES + 127) / 128;          // 391

    k_prep<<<PB, 256>>>(x, Wl1, Wl2, dst);  // pad + zero + transpose + hist
    k_scan<<<SCAN_NB, SCAN_B>>>();          // fused reduce+barrier+scan; re-zeroes g_deg
    k_scatter<<<E4B, 256>>>(src, dst);

    // layer 1 (padded to 32 ch; channel 31 is exactly zero everywhere)
    k_aggr32<<<WB, 256>>>(xpad, t, aggr);
    k_lin<C_PAD, IN_CH><<<LB, 256>>>(xpad, aggr, W1r, b1, W1s, batch, 0, bufA);

    // layer 2
    k_aggr64<<<WB, 256>>>(bufA, t, aggr);
    k_lin<HID, HID><<<LB, 256>>>(bufA, aggr, W2r, b2, W2s, batch, HID, bufB);

    // layer 3
    k_aggr64<<<WB, 256>>>(bufB, t, aggr);
    k_lin<HID, HID><<<LB, 256>>>(bufB, aggr, W3r, b3, W3s, batch, 2 * HID, bufA);

    k_final<<<N_GRAPHS, 192>>>(bl1, bl2, out);
    (void)in_sizes; (void)n_in; (void)out_size;
}